// round 2
// baseline (speedup 1.0000x reference)
#include <cuda_runtime.h>

// TVConv: per-pixel spatially-varying 3x3 depthwise conv.
// x:  (B=8, C=96, H=128, W=128) f32
// wm: (1, C=96, 3, 3, H=128, W=128) f32
// out:(B, C, H, W) f32
//
// Strategy: one thread per (c,h,w). Load the 9 per-pixel weights into
// registers ONCE, then loop over the 8 batches. This cuts weight-map DRAM
// traffic 8x (it has no batch dim). All global accesses are unit-stride in w
// -> fully coalesced. Boundary taps are predicated (zero pad).

namespace {
constexpr int B = 8;
constexpr int C = 96;
constexpr int H = 128;
constexpr int W = 128;
constexpr int HW = H * W;

__global__ __launch_bounds__(256, 8)
void tvconv_kernel(const float* __restrict__ x,
                   const float* __restrict__ wm,
                   float* __restrict__ out) {
    const int w = blockIdx.x * 32 + threadIdx.x;   // 0..127
    const int h = blockIdx.y * 8 + threadIdx.y;    // 0..127
    const int c = blockIdx.z;                      // 0..95

    const int pix = h * W + w;

    // Load 9 spatially-varying weights for this (c,h,w) into registers.
    const float* wmc = wm + (size_t)c * 9 * HW + pix;
    float k[9];
#pragma unroll
    for (int t = 0; t < 9; ++t) k[t] = wmc[(size_t)t * HW];

    // Precompute tap validity (zero padding at borders).
    const bool hm = (h > 0), hp = (h < H - 1);
    const bool wm_ok = (w > 0), wp = (w < W - 1);

    const float* xc = x + (size_t)c * HW + pix;   // batch 0, this channel, this pixel
    float* oc = out + (size_t)c * HW + pix;

#pragma unroll
    for (int b = 0; b < B; ++b) {
        const float* xb = xc + (size_t)b * C * HW;
        float acc = 0.f;

        // row h-1
        if (hm) {
            const float* r = xb - W;
            if (wm_ok) acc += k[0] * r[-1];
            acc += k[1] * r[0];
            if (wp)    acc += k[2] * r[1];
        }
        // row h
        {
            const float* r = xb;
            if (wm_ok) acc += k[3] * r[-1];
            acc += k[4] * r[0];
            if (wp)    acc += k[5] * r[1];
        }
        // row h+1
        if (hp) {
            const float* r = xb + W;
            if (wm_ok) acc += k[6] * r[-1];
            acc += k[7] * r[0];
            if (wp)    acc += k[8] * r[1];
        }

        oc[(size_t)b * C * HW] = acc;
    }
}
}  // namespace

extern "C" void kernel_launch(void* const* d_in, const int* in_sizes, int n_in,
                              void* d_out, int out_size) {
    const float* x  = (const float*)d_in[0];
    const float* wm = (const float*)d_in[1];
    float* out = (float*)d_out;

    dim3 block(32, 8, 1);
    dim3 grid(W / 32, H / 8, C);   // (4, 16, 96)
    tvconv_kernel<<<grid, block>>>(x, wm, out);
}

// round 3
// speedup vs baseline: 1.4466x; 1.4466x over previous
#include <cuda_runtime.h>

// TVConv: per-pixel spatially-varying 3x3 depthwise conv, float4-vectorized.
// x:  (B=8, C=96, H=128, W=128) f32
// wm: (1, C=96, 3, 3, H=128, W=128) f32
// out:(B, C, H, W) f32
//
// One thread computes 4 consecutive w-pixels for all 8 batches.
// - 9 float4 weight loads per thread (weights reused across batches: 8x
//   traffic saving preserved).
// - Per batch: 3 float4 row loads + <=6 scalar halo loads (halo scalars are
//   L1 hits on lines the neighboring threads' vector loads fetch).
// - No min-blocks launch bound: let ptxas keep ~70 regs for load-level
//   parallelism across the unrolled batch loop.

namespace {
constexpr int B = 8;
constexpr int C = 96;
constexpr int H = 128;
constexpr int W = 128;
constexpr int HW = H * W;

__global__ __launch_bounds__(256)
void tvconv_kernel(const float* __restrict__ x,
                   const float* __restrict__ wm,
                   float* __restrict__ out) {
    const int tx = threadIdx.x;               // 0..31 -> w in float4 units
    const int w0 = tx * 4;                    // 0,4,...,124
    const int h  = blockIdx.y * 8 + threadIdx.y;
    const int c  = blockIdx.z;

    const int pix = h * W + w0;               // 16B aligned

    // 9 spatially-varying weight vectors for these 4 pixels.
    const float4* wmv = reinterpret_cast<const float4*>(wm + (size_t)c * 9 * HW + pix);
    float4 k[9];
#pragma unroll
    for (int t = 0; t < 9; ++t) k[t] = wmv[(size_t)t * (HW / 4)];

    const bool hm = (h > 0), hp = (h < H - 1);
    const bool wl = (w0 > 0), wr = (w0 + 4 < W);

    const float* xc = x   + (size_t)c * HW + pix;
    float*       oc = out + (size_t)c * HW + pix;

#pragma unroll
    for (int b = 0; b < B; ++b) {
        const float* xb = xc + (size_t)b * C * HW;

        float4 vm1 = make_float4(0.f, 0.f, 0.f, 0.f);
        float4 vp1 = make_float4(0.f, 0.f, 0.f, 0.f);
        float  Lm1 = 0.f, L0 = 0.f, Lp1 = 0.f;
        float  Rm1 = 0.f, R0 = 0.f, Rp1 = 0.f;

        const float4 v0 = *reinterpret_cast<const float4*>(xb);
        if (wl) L0 = xb[-1];
        if (wr) R0 = xb[4];
        if (hm) {
            vm1 = *reinterpret_cast<const float4*>(xb - W);
            if (wl) Lm1 = xb[-W - 1];
            if (wr) Rm1 = xb[-W + 4];
        }
        if (hp) {
            vp1 = *reinterpret_cast<const float4*>(xb + W);
            if (wl) Lp1 = xb[W - 1];
            if (wr) Rp1 = xb[W + 4];
        }

        float4 acc;
        // lane 0: taps (w-1, w, w+1) = (L, v.x, v.y)
        acc.x = k[0].x * Lm1   + k[1].x * vm1.x + k[2].x * vm1.y
              + k[3].x * L0    + k[4].x * v0.x  + k[5].x * v0.y
              + k[6].x * Lp1   + k[7].x * vp1.x + k[8].x * vp1.y;
        // lane 1: (v.x, v.y, v.z)
        acc.y = k[0].y * vm1.x + k[1].y * vm1.y + k[2].y * vm1.z
              + k[3].y * v0.x  + k[4].y * v0.y  + k[5].y * v0.z
              + k[6].y * vp1.x + k[7].y * vp1.y + k[8].y * vp1.z;
        // lane 2: (v.y, v.z, v.w)
        acc.z = k[0].z * vm1.y + k[1].z * vm1.z + k[2].z * vm1.w
              + k[3].z * v0.y  + k[4].z * v0.z  + k[5].z * v0.w
              + k[6].z * vp1.y + k[7].z * vp1.z + k[8].z * vp1.w;
        // lane 3: (v.z, v.w, R)
        acc.w = k[0].w * vm1.z + k[1].w * vm1.w + k[2].w * Rm1
              + k[3].w * v0.z  + k[4].w * v0.w  + k[5].w * R0
              + k[6].w * vp1.z + k[7].w * vp1.w + k[8].w * Rp1;

        *reinterpret_cast<float4*>(oc + (size_t)b * C * HW) = acc;
    }
}
}  // namespace

extern "C" void kernel_launch(void* const* d_in, const int* in_sizes, int n_in,
                              void* d_out, int out_size) {
    const float* x  = (const float*)d_in[0];
    const float* wm = (const float*)d_in[1];
    float* out = (float*)d_out;

    dim3 block(32, 8, 1);        // 32 threads cover W=128 as float4
    dim3 grid(1, H / 8, C);      // (1, 16, 96)
    tvconv_kernel<<<grid, block>>>(x, wm, out);
}